// round 12
// baseline (speedup 1.0000x reference)
#include <cuda_runtime.h>
#include <math.h>

#define NB 512
#define ND 512
#define EPSF 1e-6f
#define HEPS (0.5f*1e-6f)
#define NTILES 256
#define NBLK 296

typedef unsigned long long u64t;

// ---------------- f32x2 packed helpers (sm_100a) ----------------
__device__ __forceinline__ u64t pk2(float lo, float hi){ u64t r; asm("mov.b64 %0, {%1,%2};" : "=l"(r) : "f"(lo), "f"(hi)); return r; }
__device__ __forceinline__ void upk2(u64t v, float&lo, float&hi){ asm("mov.b64 {%0,%1}, %2;" : "=f"(lo), "=f"(hi) : "l"(v)); }
__device__ __forceinline__ u64t fma2_(u64t a,u64t b,u64t c){ u64t d; asm("fma.rn.f32x2 %0,%1,%2,%3;" : "=l"(d) : "l"(a),"l"(b),"l"(c)); return d; }
__device__ __forceinline__ u64t mul2_(u64t a,u64t b){ u64t d; asm("mul.rn.f32x2 %0,%1,%2;" : "=l"(d) : "l"(a),"l"(b)); return d; }
__device__ __forceinline__ u64t add2_(u64t a,u64t b){ u64t d; asm("add.rn.f32x2 %0,%1,%2;" : "=l"(d) : "l"(a),"l"(b)); return d; }
__device__ __forceinline__ float rcpa(float x){ float r; asm("rcp.approx.f32 %0, %1;" : "=f"(r) : "f"(x)); return r; }
__device__ __forceinline__ float lg2a(float x){ float r; asm("lg2.approx.f32 %0, %1;" : "=f"(r) : "f"(x)); return r; }

// ---------------- scratch ----------------
__device__ float g_n1[NB * ND];    // normalized mu1, [i][d]
__device__ float g_h1[NB * ND];    // 0.5*sigma1 + HEPS, [i][d]
__device__ float g_n2t[NB * ND];   // NEGATED normalized mu2, TRANSPOSED [d][j]
__device__ float g_h2t[NB * ND];   // 0.5*sigma2 + HEPS, TRANSPOSED [d][j]
__device__ float g_ld1[NB], g_ld2[NB];
__device__ float g_ms1[NB], g_ms2[NB];
__device__ float g_inv2[NB];
// per-tile partials: [tile-chunk 0..15][row-or-col 0..511]
__device__ float g_rm[16 * NB], g_rs[16 * NB], g_dmin[16 * NB];
__device__ float g_cm[16 * NB], g_cs[16 * NB];
__device__ float g_dd[NB], g_diagl[NB];
__device__ int   g_ctr;   // completed-block counter
__device__ int   g_tq;    // tile queue head

// ---------------- reduction helpers ----------------
__device__ __forceinline__ float wsum(float v) {
#pragma unroll
    for (int o = 16; o; o >>= 1) v += __shfl_down_sync(0xffffffffu, v, o);
    return v;
}

// ---------------- kernel 1: per-row reductions + side-1 arrays ----------------
__global__ void prep_kernel(const float* __restrict__ mu1, const float* __restrict__ s1,
                            const float* __restrict__ mu2, const float* __restrict__ s2)
{
    __shared__ float sh[3][8];
    __shared__ float s_inv;
    const int row = blockIdx.x;
    const bool first = row < NB;
    const int r = first ? row : row - NB;
    const float* mu = (first ? mu1 : mu2) + r * ND;
    const float* sg = (first ? s1 : s2) + r * ND;
    const int t = threadIdx.x;

    if (row == 0 && t == 0) { g_ctr = 0; g_tq = 0; }   // reset counters each launch

    float ssq = 0.f, lsum = 0.f, msum = 0.f;
    for (int c = t; c < ND; c += 256) {
        float x = mu[c];
        ssq += x * x;
        float sv = sg[c];
        lsum += __logf(sv + EPSF);
        msum += sv;
        if (first) g_h1[r * ND + c] = fmaf(0.5f, sv, HEPS);
    }
    ssq = wsum(ssq); lsum = wsum(lsum); msum = wsum(msum);
    const int lane = t & 31, w = t >> 5;
    if (!lane) { sh[0][w] = ssq; sh[1][w] = lsum; sh[2][w] = msum; }
    __syncthreads();
    if (t == 0) {
        float a = 0.f, b = 0.f, c2 = 0.f;
        for (int k = 0; k < 8; k++) { a += sh[0][k]; b += sh[1][k]; c2 += sh[2][k]; }
        float inv = 1.0f / fmaxf(sqrtf(a), 1e-12f);
        s_inv = inv;
        (first ? g_ld1 : g_ld2)[r] = b;
        (first ? g_ms1 : g_ms2)[r] = c2 * (1.0f / ND);
        if (!first) g_inv2[r] = -inv;
    }
    __syncthreads();
    if (first) {
        const float inv = s_inv;
        for (int c = t; c < ND; c += 256) g_n1[r * ND + c] = mu[c] * inv;
    }
}

// ---------------- kernel 2: transpose + scale side-2 arrays ----------------
__global__ void tscale_kernel(const float* __restrict__ mu2, const float* __restrict__ s2)
{
    __shared__ float tn[32][33], th[32][33];
    const int bx = blockIdx.x * 32;   // d origin
    const int by = blockIdx.y * 32;   // j origin
    const int tx = threadIdx.x, ty = threadIdx.y;   // 32 x 8
#pragma unroll
    for (int k = 0; k < 4; k++) {
        const int j = by + ty + k * 8;
        const float iv = g_inv2[j];
        tn[ty + k * 8][tx] = mu2[j * ND + bx + tx] * iv;
        th[ty + k * 8][tx] = fmaf(0.5f, s2[j * ND + bx + tx], HEPS);
    }
    __syncthreads();
#pragma unroll
    for (int k = 0; k < 4; k++) {
        const int d = bx + ty + k * 8;
        g_n2t[d * NB + by + tx] = tn[tx][ty + k * 8];
        g_h2t[d * NB + by + tx] = th[tx][ty + k * 8];
    }
}

// ---------------- kernel 3: persistent Bhattacharyya pass ----------------
// 296 blocks x 256 threads (2 anti-phase groups of 128), atomic queue over
// 256 tiles of 32x32. Microtile per thread: 2 i x 4 j (two packed f32x2 j-pairs).
#define SN1(gg,i,d) pool[(gg)*2304 + (i)*36 + (d)]
#define SS1(gg,i,d) pool[(gg)*2304 + 1152 + (i)*36 + (d)]
#define SN2(gg,d,j) pool[4608 + (gg)*2048 + (d)*32 + (j)]
#define SS2(gg,d,j) pool[4608 + (gg)*2048 + 1024 + (d)*32 + (j)]

__global__ void __launch_bounds__(256, 2) bd_kernel(const float* __restrict__ lsp,
                                                    float* __restrict__ out)
{
    __shared__ __align__(16) float pool[8704];
    __shared__ float scm[128], scs[128];
    __shared__ int s_tile;
    __shared__ int s_last;

    const int tid = threadIdx.x;
    const int g  = tid >> 7;          // group (warps 0-3 vs 4-7)
    const int t  = tid & 127;
    const int tx = t & 7, ty = t >> 3;    // 8 j-groups x 16 i-groups
    const int i0 = 2 * ty, j0 = 4 * tx;
    const float scale = lsp[0];

    for (;;) {
        if (tid == 0) s_tile = atomicAdd(&g_tq, 1);
        __syncthreads();
        const int tile = s_tile;
        if (tile >= NTILES) break;
        const int biG = tile >> 4, bjG = tile & 15;
        const int bi = biG * 32, bj = bjG * 32;

        u64t t1a[2][2], d2a[2][2], lda[2][2];
#pragma unroll
        for (int x = 0; x < 2; x++)
#pragma unroll
            for (int jp = 0; jp < 2; jp++) { t1a[x][jp] = 0ull; d2a[x][jp] = 0ull; lda[x][jp] = 0ull; }

        for (int c = 0; c < 8; c++) {
            const int dc = g * 32 + c * 64;
#pragma unroll
            for (int k = 0; k < 2; k++) {
                const int s = t + k * 128;
                const int r = s >> 3, c4 = (s & 7) * 4;
                *(float4*)&SN1(g, r, c4) = *(const float4*)&g_n1[(bi + r) * ND + dc + c4];
                *(float4*)&SS1(g, r, c4) = *(const float4*)&g_h1[(bi + r) * ND + dc + c4];
                *(float4*)&SN2(g, r, c4) = *(const float4*)&g_n2t[(dc + r) * NB + bj + c4];
                *(float4*)&SS2(g, r, c4) = *(const float4*)&g_h2t[(dc + r) * NB + bj + c4];
            }
            asm volatile("bar.sync %0, 128;" :: "r"(g + 1) : "memory");

#pragma unroll 2
            for (int dg = 0; dg < 32; dg += 4) {
                u64t bn[2][4], bq[2][4];
#pragma unroll
                for (int jp = 0; jp < 2; jp++)
#pragma unroll
                    for (int dd = 0; dd < 4; dd++) {
                        bn[jp][dd] = *(const u64t*)&SN2(g, dg + dd, j0 + 2 * jp);
                        bq[jp][dd] = *(const u64t*)&SS2(g, dg + dd, j0 + 2 * jp);
                    }
#pragma unroll
                for (int x = 0; x < 2; x++) {
                    const float4 av = *(const float4*)&SN1(g, i0 + x, dg);
                    const float4 pv = *(const float4*)&SS1(g, i0 + x, dg);
                    u64t aa[4], pp[4];
                    aa[0] = pk2(av.x, av.x); aa[1] = pk2(av.y, av.y);
                    aa[2] = pk2(av.z, av.z); aa[3] = pk2(av.w, av.w);
                    pp[0] = pk2(pv.x, pv.x); pp[1] = pk2(pv.y, pv.y);
                    pp[2] = pk2(pv.z, pv.z); pp[3] = pk2(pv.w, pv.w);
#pragma unroll
                    for (int jp = 0; jp < 2; jp++) {
                        const u64t s0  = add2_(pp[0], bq[jp][0]);
                        const u64t s1_ = add2_(pp[1], bq[jp][1]);
                        const u64t s2_ = add2_(pp[2], bq[jp][2]);
                        const u64t s3_ = add2_(pp[3], bq[jp][3]);
                        const u64t df0 = add2_(aa[0], bn[jp][0]);   // a - b (b negated)
                        const u64t df1 = add2_(aa[1], bn[jp][1]);
                        const u64t df2 = add2_(aa[2], bn[jp][2]);
                        const u64t df3 = add2_(aa[3], bn[jp][3]);
                        const u64t sq0 = mul2_(df0, df0);
                        const u64t sq1 = mul2_(df1, df1);
                        const u64t sq2 = mul2_(df2, df2);
                        const u64t sq3 = mul2_(df3, df3);
                        d2a[x][jp] = add2_(d2a[x][jp], add2_(add2_(sq0, sq1), add2_(sq2, sq3)));
                        const u64t p01 = mul2_(s0, s1_);
                        const u64t p23 = mul2_(s2_, s3_);
                        const u64t P   = mul2_(p01, p23);
                        float Pl, Ph; upk2(P, Pl, Ph);
                        lda[x][jp] = add2_(lda[x][jp], pk2(lg2a(Pl), lg2a(Ph)));
                        const u64t rP  = pk2(rcpa(Pl), rcpa(Ph));
                        u64t N01 = mul2_(sq0, s1_); N01 = fma2_(sq1, s0,  N01);
                        u64t N23 = mul2_(sq2, s3_); N23 = fma2_(sq3, s2_, N23);
                        u64t N   = mul2_(N01, p23); N   = fma2_(N23, p01, N);
                        t1a[x][jp] = fma2_(N, rP, t1a[x][jp]);
                    }
                }
            }
            asm volatile("bar.sync %0, 128;" :: "r"(g + 1) : "memory");
        }

        // ---- combine group partials ----
        __syncthreads();
        u64t (*comb)[12] = (u64t (*)[12])&pool[0];
        if (g == 1) {
#pragma unroll
            for (int x = 0; x < 2; x++)
#pragma unroll
                for (int jp = 0; jp < 2; jp++) {
                    const int o = 6 * x + 3 * jp;
                    comb[t][o]     = t1a[x][jp];
                    comb[t][o + 1] = d2a[x][jp];
                    comb[t][o + 2] = lda[x][jp];
                }
        }
        __syncthreads();
        if (g == 0) {
#pragma unroll
            for (int x = 0; x < 2; x++)
#pragma unroll
                for (int jp = 0; jp < 2; jp++) {
                    const int o = 6 * x + 3 * jp;
                    t1a[x][jp] = add2_(t1a[x][jp], comb[t][o]);
                    d2a[x][jp] = add2_(d2a[x][jp], comb[t][o + 1]);
                    lda[x][jp] = add2_(lda[x][jp], comb[t][o + 2]);
                }
        }
        __syncthreads();   // comb read done; pool free for next tile

        if (g == 0) {
            // ---- epilogue: logits + fused row/col partials (registers + scm/scs only) ----
            float lv[2][4], dv[2][4];
#pragma unroll
            for (int x = 0; x < 2; x++) {
                const int i = bi + i0 + x;
                const float ld1v = g_ld1[i];
#pragma unroll
                for (int jp = 0; jp < 2; jp++) {
                    const int j = bj + j0 + 2 * jp;
                    float tA, tB, dA, dB, lA, lB;
                    upk2(t1a[x][jp], tA, tB);
                    upk2(d2a[x][jp], dA, dB);
                    upk2(lda[x][jp], lA, lB);
                    const float t2A = lA * (float)M_LN2 - 0.5f * (ld1v + g_ld2[j]);
                    const float t2B = lB * (float)M_LN2 - 0.5f * (ld1v + g_ld2[j + 1]);
                    const float bdA = fmaf(0.125f, tA, 0.5f * t2A);
                    const float bdB = fmaf(0.125f, tB, 0.5f * t2B);
                    lv[x][2 * jp]     = scale * __expf(-bdA * (1.0f / ND));
                    lv[x][2 * jp + 1] = scale * __expf(-bdB * (1.0f / ND));
                    dv[x][2 * jp]     = dA;
                    dv[x][2 * jp + 1] = dB;
                }
            }

            // row partials: reduce over the 8 tx lanes (consecutive lanes, xor 4/2/1)
#pragma unroll
            for (int x = 0; x < 2; x++) {
                const int i = bi + i0 + x;
                float rm = fmaxf(fmaxf(lv[x][0], lv[x][1]), fmaxf(lv[x][2], lv[x][3]));
#pragma unroll
                for (int off = 4; off; off >>= 1) rm = fmaxf(rm, __shfl_xor_sync(0xffffffffu, rm, off));
                float rs = __expf(lv[x][0] - rm) + __expf(lv[x][1] - rm)
                         + __expf(lv[x][2] - rm) + __expf(lv[x][3] - rm);
#pragma unroll
                for (int off = 4; off; off >>= 1) rs += __shfl_xor_sync(0xffffffffu, rs, off);
                float dm = 1e30f;
#pragma unroll
                for (int jj = 0; jj < 4; jj++) {
                    const int j = bj + j0 + jj;
                    dm = fminf(dm, (j == i) ? 1e30f : dv[x][jj]);
                    if (j == i) { g_dd[i] = dv[x][jj]; g_diagl[i] = lv[x][jj]; }
                }
#pragma unroll
                for (int off = 4; off; off >>= 1) dm = fminf(dm, __shfl_xor_sync(0xffffffffu, dm, off));
                if (tx == 0) {
                    g_rm[bjG * NB + i]   = rm;
                    g_rs[bjG * NB + i]   = rs;
                    g_dmin[bjG * NB + i] = dm;
                }
            }

            // col partials: per-thread over 2 i's, merge ty via xor 8/16, then 4 warps via smem
            const int w = t >> 5;
            float cmv[4], csv[4];
#pragma unroll
            for (int jj = 0; jj < 4; jj++) {
                float cm = fmaxf(lv[0][jj], lv[1][jj]);
                float cs = __expf(lv[0][jj] - cm) + __expf(lv[1][jj] - cm);
#pragma unroll
                for (int off = 8; off <= 16; off <<= 1) {
                    const float om = __shfl_xor_sync(0xffffffffu, cm, off);
                    const float os = __shfl_xor_sync(0xffffffffu, cs, off);
                    const float nm = fmaxf(cm, om);
                    cs = cs * __expf(cm - nm) + os * __expf(om - nm);
                    cm = nm;
                }
                cmv[jj] = cm; csv[jj] = cs;
            }
            if ((t & 31) < 8) {
#pragma unroll
                for (int jj = 0; jj < 4; jj++) {
                    scm[w * 32 + j0 + jj] = cmv[jj];
                    scs[w * 32 + j0 + jj] = csv[jj];
                }
            }
            asm volatile("bar.sync 1, 128;" ::: "memory");
            if (t < 32) {
                float m = scm[t], s = scs[t];
#pragma unroll
                for (int k = 1; k < 4; k++) {
                    const float om = scm[k * 32 + t], os = scs[k * 32 + t];
                    const float nm = fmaxf(m, om);
                    s = s * __expf(m - nm) + os * __expf(om - nm);
                    m = nm;
                }
                g_cm[biG * NB + bj + t] = m;
                g_cs[biG * NB + bj + t] = s;
            }
        }
    }

    // ---- last-block final reduction (all 256 threads) ----
    __threadfence();
    __syncthreads();
    if (tid == 0) s_last = (atomicAdd(&g_ctr, 1) == NBLK - 1);
    __syncthreads();
    if (!s_last) return;
    __threadfence();

    float acc[6] = {0.f, 0.f, 0.f, 0.f, 0.f, 0.f};
#pragma unroll
    for (int rr = 0; rr < 2; rr++) {
        const int idx = tid + rr * 256;
        float M = -1e30f;
#pragma unroll
        for (int k = 0; k < 16; k++) M = fmaxf(M, g_rm[k * NB + idx]);
        float S = 0.f;
#pragma unroll
        for (int k = 0; k < 16; k++) S += g_rs[k * NB + idx] * __expf(g_rm[k * NB + idx] - M);
        const float lse_row = M + __logf(S);

        float Mc = -1e30f;
#pragma unroll
        for (int k = 0; k < 16; k++) Mc = fmaxf(Mc, g_cm[k * NB + idx]);
        float Sc = 0.f;
#pragma unroll
        for (int k = 0; k < 16; k++) Sc += g_cs[k * NB + idx] * __expf(g_cm[k * NB + idx] - Mc);
        const float lse_col = Mc + __logf(Sc);

        float dmin = 1e30f;
#pragma unroll
        for (int k = 0; k < 16; k++) dmin = fminf(dmin, g_dmin[k * NB + idx]);
        const float u = __expf(-__expf(dmin - g_dd[idx]));   // exp(-diag_sim2/negmax)

        const float diag = g_diagl[idx];
        const float as = 0.5f * (g_ms1[idx] + g_ms2[idx]);
        acc[0] += lse_row - diag;
        acc[1] += lse_col - diag;
        acc[2] += u;
        acc[3] += u * u;
        acc[4] += as * as;
        acc[5] += u * as;
    }

    float* fsh = &pool[0];   // [6][8]
    const int lane = tid & 31, w8 = tid >> 5;
#pragma unroll
    for (int k = 0; k < 6; k++) {
        const float r = wsum(acc[k]);
        if (!lane) fsh[k * 8 + w8] = r;
    }
    __syncthreads();
    if (tid == 0) {
        float s[6];
        for (int k = 0; k < 6; k++) {
            float a = 0.f;
            for (int q = 0; q < 8; q++) a += fsh[k * 8 + q];
            s[k] = a;
        }
        const float loss_pro = 0.5f * ((s[0] + s[1]) * (1.0f / NB));
        const float cosv = s[5] / (fmaxf(sqrtf(s[3]), 1e-12f) * fmaxf(sqrtf(s[4]), 1e-12f));
        out[0] = loss_pro;
        out[1] = 2.4f * (1.0f - cosv);
        out[2] = 0.5f * (s[2] * (1.0f / NB));
    }
}

// ---------------- launch ----------------
extern "C" void kernel_launch(void* const* d_in, const int* in_sizes, int n_in,
                              void* d_out, int out_size)
{
    const float* mu1 = (const float*)d_in[0];
    const float* s1  = (const float*)d_in[1];
    const float* mu2 = (const float*)d_in[2];
    const float* s2  = (const float*)d_in[3];
    const float* ls  = (const float*)d_in[4];
    float* out = (float*)d_out;

    prep_kernel<<<2 * NB, 256>>>(mu1, s1, mu2, s2);
    tscale_kernel<<<dim3(16, 16), dim3(32, 8)>>>(mu2, s2);
    bd_kernel<<<NBLK, 256>>>(ls, out);
}

// round 13
// speedup vs baseline: 1.0203x; 1.0203x over previous
#include <cuda_runtime.h>
#include <math.h>

#define NB 512
#define ND 512
#define EPSF 1e-6f
#define HEPS (0.5f*1e-6f)

typedef unsigned long long u64t;

// ---------------- f32x2 packed helpers (sm_100a) ----------------
__device__ __forceinline__ u64t pk2(float lo, float hi){ u64t r; asm("mov.b64 %0, {%1,%2};" : "=l"(r) : "f"(lo), "f"(hi)); return r; }
__device__ __forceinline__ void upk2(u64t v, float&lo, float&hi){ asm("mov.b64 {%0,%1}, %2;" : "=f"(lo), "=f"(hi) : "l"(v)); }
__device__ __forceinline__ u64t fma2_(u64t a,u64t b,u64t c){ u64t d; asm("fma.rn.f32x2 %0,%1,%2,%3;" : "=l"(d) : "l"(a),"l"(b),"l"(c)); return d; }
__device__ __forceinline__ u64t mul2_(u64t a,u64t b){ u64t d; asm("mul.rn.f32x2 %0,%1,%2;" : "=l"(d) : "l"(a),"l"(b)); return d; }
__device__ __forceinline__ u64t add2_(u64t a,u64t b){ u64t d; asm("add.rn.f32x2 %0,%1,%2;" : "=l"(d) : "l"(a),"l"(b)); return d; }
__device__ __forceinline__ float rcpa(float x){ float r; asm("rcp.approx.f32 %0, %1;" : "=f"(r) : "f"(x)); return r; }
__device__ __forceinline__ float lg2a(float x){ float r; asm("lg2.approx.f32 %0, %1;" : "=f"(r) : "f"(x)); return r; }

// ---------------- scratch ----------------
__device__ float g_n1[NB * ND];    // normalized mu1, [i][d]
__device__ float g_h1[NB * ND];    // 0.5*sigma1 + HEPS, [i][d]
__device__ float g_n2t[NB * ND];   // NEGATED normalized mu2, TRANSPOSED [d][j]
__device__ float g_h2t[NB * ND];   // 0.5*sigma2 + HEPS, TRANSPOSED [d][j]
__device__ float g_ld1[NB], g_ld2[NB];
__device__ float g_ms1[NB], g_ms2[NB];
__device__ float g_inv2[NB];
// per-block partials: [chunk 0..15][row-or-col 0..511]
__device__ float g_rm[16 * NB], g_rs[16 * NB], g_dmin[16 * NB];
__device__ float g_cm[16 * NB], g_cs[16 * NB];
__device__ float g_dd[NB], g_diagl[NB];
__device__ float g_f6[6 * NB];

// ---------------- reduction helpers ----------------
__device__ __forceinline__ float wsum(float v) {
#pragma unroll
    for (int o = 16; o; o >>= 1) v += __shfl_down_sync(0xffffffffu, v, o);
    return v;
}

// ---------------- kernel 1: per-row reductions + side-1 arrays ----------------
__global__ void prep_kernel(const float* __restrict__ mu1, const float* __restrict__ s1,
                            const float* __restrict__ mu2, const float* __restrict__ s2)
{
    __shared__ float sh[3][8];
    __shared__ float s_inv;
    const int row = blockIdx.x;
    const bool first = row < NB;
    const int r = first ? row : row - NB;
    const float* mu = (first ? mu1 : mu2) + r * ND;
    const float* sg = (first ? s1 : s2) + r * ND;
    const int t = threadIdx.x;

    float ssq = 0.f, lsum = 0.f, msum = 0.f;
    for (int c = t; c < ND; c += 256) {
        float x = mu[c];
        ssq += x * x;
        float sv = sg[c];
        lsum += __logf(sv + EPSF);
        msum += sv;
        if (first) g_h1[r * ND + c] = fmaf(0.5f, sv, HEPS);
    }
    ssq = wsum(ssq); lsum = wsum(lsum); msum = wsum(msum);
    const int lane = t & 31, w = t >> 5;
    if (!lane) { sh[0][w] = ssq; sh[1][w] = lsum; sh[2][w] = msum; }
    __syncthreads();
    if (t == 0) {
        float a = 0.f, b = 0.f, c2 = 0.f;
        for (int k = 0; k < 8; k++) { a += sh[0][k]; b += sh[1][k]; c2 += sh[2][k]; }
        float inv = 1.0f / fmaxf(sqrtf(a), 1e-12f);
        s_inv = inv;
        (first ? g_ld1 : g_ld2)[r] = b;
        (first ? g_ms1 : g_ms2)[r] = c2 * (1.0f / ND);
        if (!first) g_inv2[r] = -inv;
    }
    __syncthreads();
    if (first) {
        const float inv = s_inv;
        for (int c = t; c < ND; c += 256) g_n1[r * ND + c] = mu[c] * inv;
    }
}

// ---------------- kernel 2: transpose + scale side-2 arrays ----------------
__global__ void tscale_kernel(const float* __restrict__ mu2, const float* __restrict__ s2)
{
    __shared__ float tn[32][33], th[32][33];
    const int bx = blockIdx.x * 32;   // d origin
    const int by = blockIdx.y * 32;   // j origin
    const int tx = threadIdx.x, ty = threadIdx.y;   // 32 x 8
#pragma unroll
    for (int k = 0; k < 4; k++) {
        const int j = by + ty + k * 8;
        const float iv = g_inv2[j];
        tn[ty + k * 8][tx] = mu2[j * ND + bx + tx] * iv;
        th[ty + k * 8][tx] = fmaf(0.5f, s2[j * ND + bx + tx], HEPS);
    }
    __syncthreads();
#pragma unroll
    for (int k = 0; k < 4; k++) {
        const int d = bx + ty + k * 8;
        g_n2t[d * NB + by + tx] = tn[tx][ty + k * 8];
        g_h2t[d * NB + by + tx] = th[tx][ty + k * 8];
    }
}

// ---------------- kernel 3: Bhattacharyya O(B^2 D) pass + fused partials ----------------
// 32x32 tile, 256 threads = 2 anti-phase groups of 128 (warps 0-3 / 4-7) splitting D.
#define SN1(gg,i,d) pool[(gg)*2304 + (i)*36 + (d)]
#define SS1(gg,i,d) pool[(gg)*2304 + 1152 + (i)*36 + (d)]
#define SN2(gg,d,j) pool[4608 + (gg)*2048 + (d)*32 + (j)]
#define SS2(gg,d,j) pool[4608 + (gg)*2048 + 1024 + (d)*32 + (j)]

__global__ void __launch_bounds__(256, 2) bd_kernel(const float* __restrict__ lsp)
{
    __shared__ __align__(16) float pool[8704];

    const int bi = blockIdx.y * 32, bj = blockIdx.x * 32;
    const int tid = threadIdx.x;
    const int g  = tid >> 7;          // group (warps 0-3 vs 4-7)
    const int t  = tid & 127;
    const int tx = t & 15, ty = t >> 4;
    const int i0 = 4 * ty, j0 = 2 * tx;

    u64t t1a[4], d2a[4], lda[4];
#pragma unroll
    for (int x = 0; x < 4; x++) { t1a[x] = 0ull; d2a[x] = 0ull; lda[x] = 0ull; }

    for (int c = 0; c < 8; c++) {
        const int dc = g * 32 + c * 64;
        // loader: 2 x float4 per array per thread (32 rows x 8 segs)
#pragma unroll
        for (int k = 0; k < 2; k++) {
            const int s = t + k * 128;
            const int r = s >> 3, c4 = (s & 7) * 4;
            *(float4*)&SN1(g, r, c4) = *(const float4*)&g_n1[(bi + r) * ND + dc + c4];
            *(float4*)&SS1(g, r, c4) = *(const float4*)&g_h1[(bi + r) * ND + dc + c4];
            *(float4*)&SN2(g, r, c4) = *(const float4*)&g_n2t[(dc + r) * NB + bj + c4];
            *(float4*)&SS2(g, r, c4) = *(const float4*)&g_h2t[(dc + r) * NB + bj + c4];
        }
        asm volatile("bar.sync %0, 128;" :: "r"(g + 1) : "memory");

#pragma unroll 2
        for (int dg = 0; dg < 32; dg += 4) {
            u64t bn[4], bq[4];
#pragma unroll
            for (int dd = 0; dd < 4; dd++) {
                bn[dd] = *(const u64t*)&SN2(g, dg + dd, j0);
                bq[dd] = *(const u64t*)&SS2(g, dg + dd, j0);
            }
#pragma unroll
            for (int x = 0; x < 4; x++) {
                const float4 av = *(const float4*)&SN1(g, i0 + x, dg);
                const float4 pv = *(const float4*)&SS1(g, i0 + x, dg);
                const u64t s0  = add2_(pk2(pv.x, pv.x), bq[0]);
                const u64t s1_ = add2_(pk2(pv.y, pv.y), bq[1]);
                const u64t s2_ = add2_(pk2(pv.z, pv.z), bq[2]);
                const u64t s3_ = add2_(pk2(pv.w, pv.w), bq[3]);
                const u64t df0 = add2_(pk2(av.x, av.x), bn[0]);   // a - b (b negated)
                const u64t df1 = add2_(pk2(av.y, av.y), bn[1]);
                const u64t df2 = add2_(pk2(av.z, av.z), bn[2]);
                const u64t df3 = add2_(pk2(av.w, av.w), bn[3]);
                const u64t sq0 = mul2_(df0, df0);
                const u64t sq1 = mul2_(df1, df1);
                const u64t sq2 = mul2_(df2, df2);
                const u64t sq3 = mul2_(df3, df3);
                d2a[x] = add2_(d2a[x], add2_(add2_(sq0, sq1), add2_(sq2, sq3)));
                // numerator-pair Montgomery: sum sq_d/s_d = N/P, one rcp per 4 d's
                const u64t p01 = mul2_(s0, s1_);
                const u64t p23 = mul2_(s2_, s3_);
                const u64t P   = mul2_(p01, p23);
                float Pl, Ph; upk2(P, Pl, Ph);
                lda[x] = add2_(lda[x], pk2(lg2a(Pl), lg2a(Ph)));
                const u64t rP  = pk2(rcpa(Pl), rcpa(Ph));
                u64t N01 = mul2_(sq0, s1_); N01 = fma2_(sq1, s0,  N01);
                u64t N23 = mul2_(sq2, s3_); N23 = fma2_(sq3, s2_, N23);
                u64t N   = mul2_(N01, p23); N   = fma2_(N23, p01, N);
                t1a[x] = fma2_(N, rP, t1a[x]);
            }
        }
        asm volatile("bar.sync %0, 128;" :: "r"(g + 1) : "memory");
    }

    // ---- combine group partials ----
    __syncthreads();
    u64t (*comb)[12] = (u64t (*)[12])&pool[0];
    if (g == 1) {
#pragma unroll
        for (int x = 0; x < 4; x++) {
            comb[t][3 * x]     = t1a[x];
            comb[t][3 * x + 1] = d2a[x];
            comb[t][3 * x + 2] = lda[x];
        }
    }
    __syncthreads();
    if (g == 1) return;

    // ---- group 0: epilogue (logits + fused row/col partials) ----
#pragma unroll
    for (int x = 0; x < 4; x++) {
        t1a[x] = add2_(t1a[x], comb[t][3 * x]);
        d2a[x] = add2_(d2a[x], comb[t][3 * x + 1]);
        lda[x] = add2_(lda[x], comb[t][3 * x + 2]);
    }
    const float scale = lsp[0];
    const int j = bj + j0;
    const float ld2A = g_ld2[j], ld2B = g_ld2[j + 1];
    float lv[4][2], dv[4][2];
#pragma unroll
    for (int x = 0; x < 4; x++) {
        const int i = bi + i0 + x;
        const float ld1v = g_ld1[i];
        float tA, tB, dA, dB, lA, lB;
        upk2(t1a[x], tA, tB);
        upk2(d2a[x], dA, dB);
        upk2(lda[x], lA, lB);
        const float t2A = lA * (float)M_LN2 - 0.5f * (ld1v + ld2A);
        const float t2B = lB * (float)M_LN2 - 0.5f * (ld1v + ld2B);
        const float bdA = fmaf(0.125f, tA, 0.5f * t2A);
        const float bdB = fmaf(0.125f, tB, 0.5f * t2B);
        lv[x][0] = scale * __expf(-bdA * (1.0f / ND));
        lv[x][1] = scale * __expf(-bdB * (1.0f / ND));
        dv[x][0] = dA;
        dv[x][1] = dB;
    }

    // row partials: reduce over the 16 tx lanes (half-warp xor shuffles)
    const int bjG = blockIdx.x, biG = blockIdx.y;
#pragma unroll
    for (int x = 0; x < 4; x++) {
        const int i = bi + i0 + x;
        float rm = fmaxf(lv[x][0], lv[x][1]);
#pragma unroll
        for (int off = 8; off; off >>= 1) rm = fmaxf(rm, __shfl_xor_sync(0xffffffffu, rm, off));
        float rs = __expf(lv[x][0] - rm) + __expf(lv[x][1] - rm);
#pragma unroll
        for (int off = 8; off; off >>= 1) rs += __shfl_xor_sync(0xffffffffu, rs, off);
        float mA = (j == i)     ? 1e30f : dv[x][0];
        float mB = (j + 1 == i) ? 1e30f : dv[x][1];
        float dm = fminf(mA, mB);
#pragma unroll
        for (int off = 8; off; off >>= 1) dm = fminf(dm, __shfl_xor_sync(0xffffffffu, dm, off));
        if (tx == 0) {
            g_rm[bjG * NB + i]   = rm;
            g_rs[bjG * NB + i]   = rs;
            g_dmin[bjG * NB + i] = dm;
        }
        if (j == i)     { g_dd[i] = dv[x][0]; g_diagl[i] = lv[x][0]; }
        if (j + 1 == i) { g_dd[i] = dv[x][1]; g_diagl[i] = lv[x][1]; }
    }

    // col partials: per-thread over 4 i's, merge ty-pair via xor-16, then 4 warps via smem
    float* scm = &pool[4608];          // [4][32]
    float* scs = &pool[4608 + 128];
    const int w = t >> 5;
#pragma unroll
    for (int jj = 0; jj < 2; jj++) {
        float cm = fmaxf(fmaxf(lv[0][jj], lv[1][jj]), fmaxf(lv[2][jj], lv[3][jj]));
        float cs = __expf(lv[0][jj] - cm) + __expf(lv[1][jj] - cm)
                 + __expf(lv[2][jj] - cm) + __expf(lv[3][jj] - cm);
        const float om = __shfl_xor_sync(0xffffffffu, cm, 16);
        const float os = __shfl_xor_sync(0xffffffffu, cs, 16);
        const float nm = fmaxf(cm, om);
        cs = cs * __expf(cm - nm) + os * __expf(om - nm);
        cm = nm;
        if ((t & 31) < 16) { scm[w * 32 + j0 + jj] = cm; scs[w * 32 + j0 + jj] = cs; }
    }
    asm volatile("bar.sync 1, 128;" ::: "memory");
    if (t < 32) {
        float m = scm[t], s = scs[t];
#pragma unroll
        for (int k = 1; k < 4; k++) {
            const float om = scm[k * 32 + t], os = scs[k * 32 + t];
            const float nm = fmaxf(m, om);
            s = s * __expf(m - nm) + os * __expf(om - nm);
            m = nm;
        }
        g_cm[biG * NB + bj + t] = m;
        g_cs[biG * NB + bj + t] = s;
    }
}

// ---------------- kernel 4: parallel partial-combine (16 blocks x 128 thr) ----------------
// 4 lanes per row; each lane folds 4 of the 16 chunk-partials; xor-1/2 merge.
__global__ void final1_kernel()
{
    const int idx = blockIdx.x * 128 + threadIdx.x;   // 0..2047
    const int r = idx >> 2, sub = idx & 3;
    const int k0 = sub * 4;

    float m = -1e30f, s = 0.f, mc = -1e30f, sc = 0.f, dmin = 1e30f;
#pragma unroll
    for (int k = k0; k < k0 + 4; k++) {
        const float rm = g_rm[k * NB + r];
        const float nm = fmaxf(m, rm);
        s = s * __expf(m - nm) + g_rs[k * NB + r] * __expf(rm - nm);
        m = nm;
        const float cm = g_cm[k * NB + r];
        const float nc = fmaxf(mc, cm);
        sc = sc * __expf(mc - nc) + g_cs[k * NB + r] * __expf(cm - nc);
        mc = nc;
        dmin = fminf(dmin, g_dmin[k * NB + r]);
    }
#pragma unroll
    for (int off = 1; off <= 2; off <<= 1) {
        const float om = __shfl_xor_sync(0xffffffffu, m, off);
        const float os = __shfl_xor_sync(0xffffffffu, s, off);
        const float nm = fmaxf(m, om);
        s = s * __expf(m - nm) + os * __expf(om - nm);
        m = nm;
        const float oc  = __shfl_xor_sync(0xffffffffu, mc, off);
        const float osc = __shfl_xor_sync(0xffffffffu, sc, off);
        const float nc = fmaxf(mc, oc);
        sc = sc * __expf(mc - nc) + osc * __expf(oc - nc);
        mc = nc;
        dmin = fminf(dmin, __shfl_xor_sync(0xffffffffu, dmin, off));
    }
    if (sub == 0) {
        const float lse_row = m + __logf(s);
        const float lse_col = mc + __logf(sc);
        const float u = __expf(-__expf(dmin - g_dd[r]));   // exp(-diag_sim2/negmax)
        const float diag = g_diagl[r];
        const float as = 0.5f * (g_ms1[r] + g_ms2[r]);
        g_f6[0 * NB + r] = lse_row - diag;
        g_f6[1 * NB + r] = lse_col - diag;
        g_f6[2 * NB + r] = u;
        g_f6[3 * NB + r] = u * u;
        g_f6[4 * NB + r] = as * as;
        g_f6[5 * NB + r] = u * as;
    }
}

// ---------------- kernel 5: tiny scalar reduction ----------------
__global__ void final2_kernel(float* __restrict__ out)
{
    __shared__ float fsh[6][16];
    const int t = threadIdx.x;   // 512 threads
    float v[6];
#pragma unroll
    for (int k = 0; k < 6; k++) v[k] = g_f6[k * NB + t];
    const int lane = t & 31, w = t >> 5;
#pragma unroll
    for (int k = 0; k < 6; k++) {
        const float r = wsum(v[k]);
        if (!lane) fsh[k][w] = r;
    }
    __syncthreads();
    if (t == 0) {
        float s[6];
        for (int k = 0; k < 6; k++) {
            float a = 0.f;
            for (int q = 0; q < 16; q++) a += fsh[k][q];
            s[k] = a;
        }
        const float loss_pro = 0.5f * ((s[0] + s[1]) * (1.0f / NB));
        const float cosv = s[5] / (fmaxf(sqrtf(s[3]), 1e-12f) * fmaxf(sqrtf(s[4]), 1e-12f));
        out[0] = loss_pro;
        out[1] = 2.4f * (1.0f - cosv);
        out[2] = 0.5f * (s[2] * (1.0f / NB));
    }
}

// ---------------- launch ----------------
extern "C" void kernel_launch(void* const* d_in, const int* in_sizes, int n_in,
                              void* d_out, int out_size)
{
    const float* mu1 = (const float*)d_in[0];
    const float* s1  = (const float*)d_in[1];
    const float* mu2 = (const float*)d_in[2];
    const float* s2  = (const float*)d_in[3];
    const float* ls  = (const float*)d_in[4];
    float* out = (float*)d_out;

    prep_kernel<<<2 * NB, 256>>>(mu1, s1, mu2, s2);
    tscale_kernel<<<dim3(16, 16), dim3(32, 8)>>>(mu2, s2);
    bd_kernel<<<dim3(16, 16), 256>>>(ls);
    final1_kernel<<<16, 128>>>();
    final2_kernel<<<1, NB>>>(out);
}